// round 8
// baseline (speedup 1.0000x reference)
#include <cuda_runtime.h>
#include <cstdint>

#define BM      128       // super-tile rows per iteration (2 x 64-row sub-tiles)
#define SUBM    64
#define KDIM    64
#define NDIM    128
#define THREADS 256
#define MAXGRID 296        // 2 persistent CTAs per SM x 148 SMs

#define STAGE_FLOATS (BM * KDIM)         // 8192 floats = 32KB per stage
#define SMEM_BYTES   (3 * STAGE_FLOATS * 4)   // 96KB, 3-stage ring

// Precomputed tf32 B fragments: [ks 0..7][nblock 0..7][lane 0..31] float4
// float4 = { b0(ntA), b1(ntA), b0(ntB), b1(ntB) } with the phi column remap.
__device__ float4 g_Bfrag[8 * 8 * 32];

__device__ __forceinline__ uint32_t f2tf32(float f) {
    uint32_t r;
    asm("cvt.rna.tf32.f32 %0, %1;" : "=r"(r) : "f"(f));
    return r;
}

__global__ void setup_kernel(const float* __restrict__ W) {
    int t = blockIdx.x * blockDim.x + threadIdx.x;   // 0..2047
    int lane = t & 31;
    int nb   = (t >> 5) & 7;     // 16-col block
    int ks   = t >> 8;           // k-step
    int qk   = lane & 3;
    int s    = lane >> 2;        // B fragment n-slot
    int colA = nb * 16 + (s >> 1) * 4 + (s & 1);
    int colB = colA + 2;
    int k0 = ks * 8 + 2 * qk;
    float4 v;
    v.x = __uint_as_float(f2tf32(W[k0 * NDIM + colA]));
    v.y = __uint_as_float(f2tf32(W[(k0 + 1) * NDIM + colA]));
    v.z = __uint_as_float(f2tf32(W[k0 * NDIM + colB]));
    v.w = __uint_as_float(f2tf32(W[(k0 + 1) * NDIM + colB]));
    g_Bfrag[t] = v;
}

// Swizzled x staging for a 128-row super-tile.
// float offset of phys float p in row:  p ^ ((row&7)<<3)
__device__ __forceinline__ void issue_tile(const float* __restrict__ x,
                                           float* xsbuf, long tile_row,
                                           long M, int tid) {
    #pragma unroll
    for (int j = 0; j < 8; ++j) {
        int idx = tid + j * THREADS;       // 0..2047
        int row = idx >> 4;                // 0..127
        int c4  = idx & 15;                // float4 column
        long grow = tile_row + row;
        bool valid = (grow < M);
        const float* src = x + (valid ? grow : 0) * KDIM + c4 * 4;
        int foff = row * KDIM + ((c4 * 4) ^ ((row & 7) << 3));
        uint32_t dst = (uint32_t)__cvta_generic_to_shared(xsbuf + foff);
        int sz = valid ? 16 : 0;
        asm volatile("cp.async.cg.shared.global [%0], [%1], 16, %2;\n"
                     :: "r"(dst), "l"(src), "r"(sz));
    }
}

extern __shared__ float xs[];   // 3 * STAGE_FLOATS

__global__ void __launch_bounds__(THREADS, 2)
dense_ragged_kernel(const float* __restrict__ x,
                    const float* __restrict__ bias,
                    float* __restrict__ out,
                    long M, int ntiles)
{
    const int tid    = threadIdx.x;
    const int lane   = tid & 31;
    const int wid    = tid >> 5;
    const int warp_m = wid & 1;           // 2 row bands of 32 (within a sub-tile)
    const int warp_n = wid >> 1;          // 4 col bands of 32
    const int qrow   = lane >> 2;         // 0..7
    const int qk     = lane & 3;          // 0..3

    // ---- persistent per-warp B fragments in registers ----
    float4 Breg[8][2];
    #pragma unroll
    for (int ks = 0; ks < 8; ++ks)
        #pragma unroll
        for (int nbi = 0; nbi < 2; ++nbi)
            Breg[ks][nbi] = g_Bfrag[(ks * 8 + warp_n * 2 + nbi) * 32 + lane];

    // ---- loop-invariant bias fragments ----
    float4 bb[2];
    #pragma unroll
    for (int nbi = 0; nbi < 2; ++nbi)
        bb[nbi] = *(const float4*)(bias + warp_n * 32 + nbi * 16 + qk * 4);

    // A-load base within a sub-tile (float units)
    const int abase = (warp_m * 32 + qrow) * KDIM + 2 * qk;
    const int g = gridDim.x;

    int it = blockIdx.x;
    // prologue: fill stages 0 and 1
    if (it < ntiles) {
        issue_tile(x, xs, (long)it * BM, M, tid);
        asm volatile("cp.async.commit_group;\n");
        if (it + g < ntiles) {
            issue_tile(x, xs + STAGE_FLOATS, (long)(it + g) * BM, M, tid);
            asm volatile("cp.async.commit_group;\n");
        }
    }

    int stage = 0;
    while (it < ntiles) {
        int n1 = it + g;          // tile occupying the next stage
        int n2 = it + 2 * g;      // tile to issue this iteration

        if (n1 < ntiles) {
            asm volatile("cp.async.wait_group 1;\n");
        } else {
            asm volatile("cp.async.wait_group 0;\n");
        }
        __syncthreads();   // single barrier per 128-row super-tile

        if (n2 < ntiles) {
            int ws = stage + 2; if (ws >= 3) ws -= 3;
            issue_tile(x, xs + ws * STAGE_FLOATS, (long)n2 * BM, M, tid);
            asm volatile("cp.async.commit_group;\n");
        }

        // ---- two 64-row sub-tiles, accumulators reused ----
        #pragma unroll
        for (int sub = 0; sub < 2; ++sub) {
            const float* xb = xs + stage * STAGE_FLOATS + sub * (SUBM * KDIM);

            float acc[2][2][8];   // [mt][nbi][ntA:0..3, ntB:4..7]
            #pragma unroll
            for (int mt = 0; mt < 2; ++mt)
                #pragma unroll
                for (int nb = 0; nb < 2; ++nb)
                    #pragma unroll
                    for (int e = 0; e < 8; ++e) acc[mt][nb][e] = 0.f;

            #pragma unroll
            for (int ks = 0; ks < 8; ++ks) {
                const int ksw = (ks ^ qrow) << 3;
                uint32_t a[2][4];
                #pragma unroll
                for (int mt = 0; mt < 2; ++mt) {
                    // raw fp32 bits: tf32 mma reads top 19 bits (HW truncation)
                    const float* p = xb + abase + mt * (16 * KDIM) + ksw;
                    uint2 v0 = *(const uint2*)(p);
                    uint2 v1 = *(const uint2*)(p + 8 * KDIM);
                    a[mt][0] = v0.x;
                    a[mt][1] = v1.x;
                    a[mt][2] = v0.y;
                    a[mt][3] = v1.y;
                }
                #pragma unroll
                for (int nbi = 0; nbi < 2; ++nbi) {
                    uint32_t bA0 = __float_as_uint(Breg[ks][nbi].x);
                    uint32_t bA1 = __float_as_uint(Breg[ks][nbi].y);
                    uint32_t bB0 = __float_as_uint(Breg[ks][nbi].z);
                    uint32_t bB1 = __float_as_uint(Breg[ks][nbi].w);
                    #pragma unroll
                    for (int mt = 0; mt < 2; ++mt) {
                        asm volatile(
                            "mma.sync.aligned.m16n8k8.row.col.f32.tf32.tf32.f32 "
                            "{%0,%1,%2,%3}, {%4,%5,%6,%7}, {%8,%9}, {%0,%1,%2,%3};\n"
                            : "+f"(acc[mt][nbi][0]), "+f"(acc[mt][nbi][1]),
                              "+f"(acc[mt][nbi][2]), "+f"(acc[mt][nbi][3])
                            : "r"(a[mt][0]), "r"(a[mt][1]), "r"(a[mt][2]), "r"(a[mt][3]),
                              "r"(bA0), "r"(bA1));
                        asm volatile(
                            "mma.sync.aligned.m16n8k8.row.col.f32.tf32.tf32.f32 "
                            "{%0,%1,%2,%3}, {%4,%5,%6,%7}, {%8,%9}, {%0,%1,%2,%3};\n"
                            : "+f"(acc[mt][nbi][4]), "+f"(acc[mt][nbi][5]),
                              "+f"(acc[mt][nbi][6]), "+f"(acc[mt][nbi][7])
                            : "r"(a[mt][0]), "r"(a[mt][1]), "r"(a[mt][2]), "r"(a[mt][3]),
                              "r"(bB0), "r"(bB1));
                    }
                }
            }

            // ---- epilogue: bias + relu + STG.128 (overlaps next sub-tile) ----
            long baser = (long)it * BM + sub * SUBM + warp_m * 32;
            #pragma unroll
            for (int mt = 0; mt < 2; ++mt) {
                long r0 = baser + mt * 16 + qrow;
                long r1 = r0 + 8;
                #pragma unroll
                for (int nbi = 0; nbi < 2; ++nbi) {
                    int c = warp_n * 32 + nbi * 16 + qk * 4;
                    if (r0 < M) {
                        float4 o;
                        o.x = fmaxf(acc[mt][nbi][0] + bb[nbi].x, 0.f);
                        o.y = fmaxf(acc[mt][nbi][1] + bb[nbi].y, 0.f);
                        o.z = fmaxf(acc[mt][nbi][4] + bb[nbi].z, 0.f);
                        o.w = fmaxf(acc[mt][nbi][5] + bb[nbi].w, 0.f);
                        __stcs((float4*)(out + r0 * NDIM + c), o);
                    }
                    if (r1 < M) {
                        float4 o;
                        o.x = fmaxf(acc[mt][nbi][2] + bb[nbi].x, 0.f);
                        o.y = fmaxf(acc[mt][nbi][3] + bb[nbi].y, 0.f);
                        o.z = fmaxf(acc[mt][nbi][6] + bb[nbi].z, 0.f);
                        o.w = fmaxf(acc[mt][nbi][7] + bb[nbi].w, 0.f);
                        __stcs((float4*)(out + r1 * NDIM + c), o);
                    }
                }
            }
        }

        it = n1;
        stage = stage + 1 == 3 ? 0 : stage + 1;
    }
}

extern "C" void kernel_launch(void* const* d_in, const int* in_sizes, int n_in,
                              void* d_out, int out_size) {
    const float* x = (const float*)d_in[0];
    const float* W = (const float*)d_in[1];
    const float* b = (const float*)d_in[2];
    float* out = (float*)d_out;

    long M = (long)in_sizes[0] / KDIM;
    int ntiles = (int)((M + BM - 1) / BM);
    int grid = ntiles < MAXGRID ? ntiles : MAXGRID;

    cudaFuncSetAttribute(dense_ragged_kernel,
                         cudaFuncAttributeMaxDynamicSharedMemorySize, SMEM_BYTES);
    setup_kernel<<<8, 256>>>(W);
    dense_ragged_kernel<<<grid, THREADS, SMEM_BYTES>>>(x, b, out, M, ntiles);
}

// round 9
// speedup vs baseline: 1.0321x; 1.0321x over previous
#include <cuda_runtime.h>
#include <cstdint>

#define BM      32        // rows per tile (CTA)
#define KDIM    64
#define NDIM    128
#define THREADS 128       // 4 warps
#define MAXGRID 592       // 4 persistent CTAs per SM x 148 SMs

#define STAGE_FLOATS (BM * KDIM)            // 2048 floats = 8KB per stage
#define SMEM_BYTES   (3 * STAGE_FLOATS * 4) // 24KB, 3-stage ring (4 CTAs = 96KB/SM)

// Precomputed tf32 B fragments: [ks 0..7][nblock 0..7][lane 0..31] float4
// float4 = { b0(ntA), b1(ntA), b0(ntB), b1(ntB) } with the phi column remap.
__device__ float4 g_Bfrag[8 * 8 * 32];

__device__ __forceinline__ uint32_t f2tf32(float f) {
    uint32_t r;
    asm("cvt.rna.tf32.f32 %0, %1;" : "=r"(r) : "f"(f));
    return r;
}

__global__ void setup_kernel(const float* __restrict__ W) {
    int t = blockIdx.x * blockDim.x + threadIdx.x;   // 0..2047
    int lane = t & 31;
    int nb   = (t >> 5) & 7;     // 16-col block
    int ks   = t >> 8;           // k-step
    int qk   = lane & 3;
    int s    = lane >> 2;        // B fragment n-slot
    int colA = nb * 16 + (s >> 1) * 4 + (s & 1);
    int colB = colA + 2;
    int k0 = ks * 8 + 2 * qk;
    float4 v;
    v.x = __uint_as_float(f2tf32(W[k0 * NDIM + colA]));
    v.y = __uint_as_float(f2tf32(W[(k0 + 1) * NDIM + colA]));
    v.z = __uint_as_float(f2tf32(W[k0 * NDIM + colB]));
    v.w = __uint_as_float(f2tf32(W[(k0 + 1) * NDIM + colB]));
    g_Bfrag[t] = v;
}

// Swizzled x-tile staging. float offset of phys float p in row:  p ^ ((row&7)<<3)
__device__ __forceinline__ void issue_tile(const float* __restrict__ x,
                                           float* xsbuf, long tile_row,
                                           long M, int tid) {
    #pragma unroll
    for (int j = 0; j < 4; ++j) {
        int idx = tid + j * THREADS;       // 0..511
        int row = idx >> 4;                // 0..31
        int c4  = idx & 15;                // float4 column
        long grow = tile_row + row;
        bool valid = (grow < M);
        const float* src = x + (valid ? grow : 0) * KDIM + c4 * 4;
        int foff = row * KDIM + ((c4 * 4) ^ ((row & 7) << 3));
        uint32_t dst = (uint32_t)__cvta_generic_to_shared(xsbuf + foff);
        int sz = valid ? 16 : 0;
        asm volatile("cp.async.cg.shared.global [%0], [%1], 16, %2;\n"
                     :: "r"(dst), "l"(src), "r"(sz));
    }
}

__global__ void __launch_bounds__(THREADS, 4)
dense_ragged_kernel(const float* __restrict__ x,
                    const float* __restrict__ bias,
                    float* __restrict__ out,
                    long M, int ntiles)
{
    __shared__ float xs[3 * STAGE_FLOATS];   // 24KB, 3-stage ring

    const int tid    = threadIdx.x;
    const int lane   = tid & 31;
    const int warp_n = tid >> 5;          // 4 col bands of 32 (warp id)
    const int qrow   = lane >> 2;         // 0..7
    const int qk     = lane & 3;          // 0..3

    // ---- persistent per-warp B fragments in registers ----
    float4 Breg[8][2];
    #pragma unroll
    for (int ks = 0; ks < 8; ++ks)
        #pragma unroll
        for (int nbi = 0; nbi < 2; ++nbi)
            Breg[ks][nbi] = g_Bfrag[(ks * 8 + warp_n * 2 + nbi) * 32 + lane];

    // ---- loop-invariant bias fragments ----
    float4 bb[2];
    #pragma unroll
    for (int nbi = 0; nbi < 2; ++nbi)
        bb[nbi] = *(const float4*)(bias + warp_n * 32 + nbi * 16 + qk * 4);

    // A-load base (float units): rows 0..31 of the tile, all warps
    const int abase = qrow * KDIM + 2 * qk;
    const int g = gridDim.x;

    int it = blockIdx.x;
    // prologue: fill stages 0 and 1
    if (it < ntiles) {
        issue_tile(x, xs, (long)it * BM, M, tid);
        asm volatile("cp.async.commit_group;\n");
        if (it + g < ntiles) {
            issue_tile(x, xs + STAGE_FLOATS, (long)(it + g) * BM, M, tid);
            asm volatile("cp.async.commit_group;\n");
        }
    }

    int stage = 0;
    while (it < ntiles) {
        int n1 = it + g;          // tile occupying the next stage
        int n2 = it + 2 * g;      // tile to issue this iteration

        if (n1 < ntiles) {
            asm volatile("cp.async.wait_group 1;\n");
        } else {
            asm volatile("cp.async.wait_group 0;\n");
        }
        __syncthreads();   // single barrier per tile (4 warps only)

        if (n2 < ntiles) {
            int ws = stage + 2; if (ws >= 3) ws -= 3;
            issue_tile(x, xs + ws * STAGE_FLOATS, (long)n2 * BM, M, tid);
            asm volatile("cp.async.commit_group;\n");
        }

        const float* xb = xs + stage * STAGE_FLOATS;
        float acc[2][2][8];   // [mt][nbi][ntA:0..3, ntB:4..7]
        #pragma unroll
        for (int mt = 0; mt < 2; ++mt)
            #pragma unroll
            for (int nb = 0; nb < 2; ++nb)
                #pragma unroll
                for (int e = 0; e < 8; ++e) acc[mt][nb][e] = 0.f;

        #pragma unroll
        for (int ks = 0; ks < 8; ++ks) {
            const int ksw = (ks ^ qrow) << 3;
            uint32_t a[2][4];
            #pragma unroll
            for (int mt = 0; mt < 2; ++mt) {
                // raw fp32 bits: tf32 mma reads top 19 bits (HW truncation)
                const float* p = xb + abase + mt * (16 * KDIM) + ksw;
                uint2 v0 = *(const uint2*)(p);
                uint2 v1 = *(const uint2*)(p + 8 * KDIM);
                a[mt][0] = v0.x;
                a[mt][1] = v1.x;
                a[mt][2] = v0.y;
                a[mt][3] = v1.y;
            }
            #pragma unroll
            for (int nbi = 0; nbi < 2; ++nbi) {
                uint32_t bA0 = __float_as_uint(Breg[ks][nbi].x);
                uint32_t bA1 = __float_as_uint(Breg[ks][nbi].y);
                uint32_t bB0 = __float_as_uint(Breg[ks][nbi].z);
                uint32_t bB1 = __float_as_uint(Breg[ks][nbi].w);
                #pragma unroll
                for (int mt = 0; mt < 2; ++mt) {
                    asm volatile(
                        "mma.sync.aligned.m16n8k8.row.col.f32.tf32.tf32.f32 "
                        "{%0,%1,%2,%3}, {%4,%5,%6,%7}, {%8,%9}, {%0,%1,%2,%3};\n"
                        : "+f"(acc[mt][nbi][0]), "+f"(acc[mt][nbi][1]),
                          "+f"(acc[mt][nbi][2]), "+f"(acc[mt][nbi][3])
                        : "r"(a[mt][0]), "r"(a[mt][1]), "r"(a[mt][2]), "r"(a[mt][3]),
                          "r"(bA0), "r"(bA1));
                    asm volatile(
                        "mma.sync.aligned.m16n8k8.row.col.f32.tf32.tf32.f32 "
                        "{%0,%1,%2,%3}, {%4,%5,%6,%7}, {%8,%9}, {%0,%1,%2,%3};\n"
                        : "+f"(acc[mt][nbi][4]), "+f"(acc[mt][nbi][5]),
                          "+f"(acc[mt][nbi][6]), "+f"(acc[mt][nbi][7])
                        : "r"(a[mt][0]), "r"(a[mt][1]), "r"(a[mt][2]), "r"(a[mt][3]),
                          "r"(bB0), "r"(bB1));
                }
            }
        }

        // ---- epilogue: bias + relu + STG.128 ----
        long baser = (long)it * BM;
        #pragma unroll
        for (int mt = 0; mt < 2; ++mt) {
            long r0 = baser + mt * 16 + qrow;
            long r1 = r0 + 8;
            #pragma unroll
            for (int nbi = 0; nbi < 2; ++nbi) {
                int c = warp_n * 32 + nbi * 16 + qk * 4;
                if (r0 < M) {
                    float4 o;
                    o.x = fmaxf(acc[mt][nbi][0] + bb[nbi].x, 0.f);
                    o.y = fmaxf(acc[mt][nbi][1] + bb[nbi].y, 0.f);
                    o.z = fmaxf(acc[mt][nbi][4] + bb[nbi].z, 0.f);
                    o.w = fmaxf(acc[mt][nbi][5] + bb[nbi].w, 0.f);
                    __stcs((float4*)(out + r0 * NDIM + c), o);
                }
                if (r1 < M) {
                    float4 o;
                    o.x = fmaxf(acc[mt][nbi][2] + bb[nbi].x, 0.f);
                    o.y = fmaxf(acc[mt][nbi][3] + bb[nbi].y, 0.f);
                    o.z = fmaxf(acc[mt][nbi][6] + bb[nbi].z, 0.f);
                    o.w = fmaxf(acc[mt][nbi][7] + bb[nbi].w, 0.f);
                    __stcs((float4*)(out + r1 * NDIM + c), o);
                }
            }
        }

        it = n1;
        stage = stage + 1 == 3 ? 0 : stage + 1;
    }
}

extern "C" void kernel_launch(void* const* d_in, const int* in_sizes, int n_in,
                              void* d_out, int out_size) {
    const float* x = (const float*)d_in[0];
    const float* W = (const float*)d_in[1];
    const float* b = (const float*)d_in[2];
    float* out = (float*)d_out;

    long M = (long)in_sizes[0] / KDIM;
    int ntiles = (int)((M + BM - 1) / BM);
    int grid = ntiles < MAXGRID ? ntiles : MAXGRID;

    setup_kernel<<<8, 256>>>(W);
    dense_ragged_kernel<<<grid, THREADS>>>(x, b, out, M, ntiles);
}